// round 13
// baseline (speedup 1.0000x reference)
#include <cuda_runtime.h>

#define HWSZ   262144
#define NIMG   128
#define AXK    26214
#define SEG    16
#define CAPB   4096
#define CAPI   (SEG*CAPB)
#define SELCAP 3072
#define R_HI   260
#define R_LO   560

// ---------------- static scratch ----------------
__device__ unsigned g_cand[(size_t)2 * NIMG * CAPI];   // 64 MB
__device__ unsigned g_bhist[2 * NIMG * 256];
__device__ unsigned g_cnt[2 * NIMG][SEG];
__device__ unsigned g_above[2 * NIMG];
__device__ unsigned g_hi[2 * NIMG], g_lo[2 * NIMG], g_thr[2 * NIMG];
__device__ unsigned g_B[2 * NIMG], g_r[2 * NIMG], g_selcnt[2 * NIMG];
__device__ unsigned g_selbuf[2 * NIMG * SELCAP];       // 3 MB
__device__ double   g_acc;

// Bit-identical squared Roberts magnitude everywhere (fixed op order).
__device__ __forceinline__ float m2_one(float a, float b, float c, float d) {
    float gx = a - d, gy = b - c;
    return fmaf(gx, gx, fmaf(gy, gy, 1e-12f));
}

__device__ __forceinline__ float asqrt(float x) {
    float r; asm("sqrt.approx.f32 %0, %1;" : "=f"(r) : "f"(x)); return r;
}

__device__ __forceinline__ unsigned bshift(unsigned width) {
    int hb = 32 - __clz(width - 1u);
    int s = hb - 8;
    return (s > 0) ? (unsigned)s : 0u;
}

__device__ __forceinline__ void quad_m2_rows(const float4& a, const float4& b,
                                             float ea, float eb, float out[4]) {
    out[0] = m2_one(a.x, a.y, b.x, b.y);
    out[1] = m2_one(a.y, a.z, b.y, b.z);
    out[2] = m2_one(a.z, a.w, b.z, b.w);
    out[3] = m2_one(a.w, ea,  b.w, eb);
}

// ---- 8-px horizontal "oct" (k_count) ----
struct Oct { float4 a0, b0, a1, b1; float ea, eb; };

__device__ __forceinline__ Oct load_oct(const float* __restrict__ img,
                                        int i, int j, int lane) {
    Oct o;
    const float* q = img + i * 512 + j;
    o.a0 = __ldg((const float4*)q);
    o.b0 = __ldg((const float4*)(q + 4));
    bool lastrow = (i == 511);
    if (!lastrow) {
        o.a1 = __ldg((const float4*)(q + 512));
        o.b1 = __ldg((const float4*)(q + 516));
    } else {
        o.a1 = make_float4(0.f, 0.f, 0.f, 0.f);
        o.b1 = make_float4(0.f, 0.f, 0.f, 0.f);
    }
    o.ea = __shfl_down_sync(0xffffffffu, o.a0.x, 1);
    o.eb = __shfl_down_sync(0xffffffffu, o.a1.x, 1);
    if (lane == 31) {
        bool hn = (j + 8) < 512;
        o.ea = hn ? __ldg(q + 8) : 0.0f;
        o.eb = (hn && !lastrow) ? __ldg(q + 520) : 0.0f;
    }
    return o;
}

__device__ __forceinline__ void oct_m2(const Oct& o, float m2[8]) {
    quad_m2_rows(o.a0, o.a1, o.b0.x, o.b1.x, m2);
    quad_m2_rows(o.b0, o.b1, o.ea,   o.eb,   m2 + 4);
}

// legacy single-quad loader (bracket only)
struct Quad { float4 v0, v1; float x4, y4; };
__device__ __forceinline__ Quad load_quad(const float* __restrict__ img, int p, int lane) {
    Quad q;
    int i = p >> 9, j = p & 511;
    q.v0 = __ldg((const float4*)(img + p));
    bool lastrow = (i == 511);
    q.v1 = lastrow ? make_float4(0.f, 0.f, 0.f, 0.f)
                   : __ldg((const float4*)(img + p + 512));
    q.x4 = __shfl_down_sync(0xffffffffu, q.v0.x, 1);
    q.y4 = __shfl_down_sync(0xffffffffu, q.v1.x, 1);
    if (lane == 31) {
        bool hn = (j + 4) < 512;
        q.x4 = hn ? __ldg(img + p + 4) : 0.0f;
        q.y4 = (hn && !lastrow) ? __ldg(img + p + 516) : 0.0f;
    }
    return q;
}
__device__ __forceinline__ void quad_m2(const Quad& q, float m2[4]) {
    m2[0] = m2_one(q.v0.x, q.v0.y, q.v1.x, q.v1.y);
    m2[1] = m2_one(q.v0.y, q.v0.z, q.v1.y, q.v1.z);
    m2[2] = m2_one(q.v0.z, q.v0.w, q.v1.z, q.v1.w);
    m2[3] = m2_one(q.v0.w, q.x4,   q.v1.w, q.y4);
}

// ---- raw 4px loads with NO shuffles (k_scan) ----
struct RawQ { float4 a, b; float ea, eb; };

__device__ __forceinline__ RawQ load_raw(const float* __restrict__ row0,
                                         bool lastrow, bool edge_thr, bool has_right) {
    RawQ r;
    r.a = __ldg((const float4*)row0);
    r.b = lastrow ? make_float4(0.f, 0.f, 0.f, 0.f)
                  : __ldg((const float4*)(row0 + 512));
    r.ea = 0.0f; r.eb = 0.0f;
    if (edge_thr && has_right) {
        r.ea = __ldg(row0 + 4);
        if (!lastrow) r.eb = __ldg(row0 + 516);
    }
    return r;
}

__device__ __forceinline__ void raw_m2(const RawQ& r, int lane, float out[4]) {
    float x4 = __shfl_down_sync(0xffffffffu, r.a.x, 1);
    float y4 = __shfl_down_sync(0xffffffffu, r.b.x, 1);
    if (lane == 31) { x4 = r.ea; y4 = r.eb; }
    out[0] = m2_one(r.a.x, r.a.y, r.b.x, r.b.y);
    out[1] = m2_one(r.a.y, r.a.z, r.b.y, r.b.z);
    out[2] = m2_one(r.a.z, r.a.w, r.b.z, r.b.w);
    out[3] = m2_one(r.a.w, x4,    r.b.w, y4);
}

// fast suffix sum of s[0..255] (warp shuffles, 2 syncs); blockDim>=256
__device__ __forceinline__ void suffix256_fast(unsigned* s, unsigned* wtot, int tid) {
    unsigned v = (tid < 256) ? s[tid] : 0u;
    int lane = tid & 31;
    #pragma unroll
    for (int off = 1; off < 32; off <<= 1) {
        unsigned t = __shfl_down_sync(0xffffffffu, v, off);
        if (lane + off < 32) v += t;
    }
    if (tid < 256 && lane == 0) wtot[tid >> 5] = v;
    __syncthreads();
    if (tid < 256) {
        unsigned hi = 0;
        int w = tid >> 5;
        #pragma unroll
        for (int x = 1; x < 8; x++) if (x > w) hi += wtot[x];
        s[tid] = v + hi;
    }
    __syncthreads();
}

// ---------------- K1: zero own counters + sampled bracket --------------------
__global__ void k_bracket(const float* __restrict__ tgt, const float* __restrict__ prd) {
    __shared__ unsigned sval[4096];
    __shared__ unsigned hist[256];
    __shared__ unsigned wtot[8];
    __shared__ unsigned s_d;
    int n = blockIdx.x, sel = blockIdx.y;
    int ns = sel * NIMG + n;
    const float* img = (sel ? prd : tgt) + (size_t)n * HWSZ;
    int tid = threadIdx.x, lane = tid & 31, wid = tid >> 5;

    g_bhist[ns * 256 + tid] = 0;
    if (tid < SEG) g_cnt[ns][tid] = 0;
    if (tid == 0) { g_above[ns] = 0; g_selcnt[ns] = 0; if (ns == 0) g_acc = 0.0; }

    #pragma unroll
    for (int k = 0; k < 4; k++) {
        int c   = k * 8 + wid;
        int row = (c * 509) & 511;
        int col = (c & 3) * 128;
        int p   = row * 512 + col + lane * 4;
        Quad q = load_quad(img, p, lane);
        float m2[4]; quad_m2(q, m2);
        int s = c * 128 + lane * 4;
        sval[s + 0] = __float_as_uint(m2[0]);
        sval[s + 1] = __float_as_uint(m2[1]);
        sval[s + 2] = __float_as_uint(m2[2]);
        sval[s + 3] = __float_as_uint(m2[3]);
    }
    __syncthreads();

    unsigned res[2]; const int ranks[2] = { R_HI, R_LO };
    for (int r = 0; r < 2; r++) {
        unsigned prefix = 0, rank = (unsigned)ranks[r];
        for (int shift = 24; shift >= 0; shift -= 8) {
            hist[tid] = 0;
            __syncthreads();
            unsigned hmask = (shift == 24) ? 0u : (0xFFFFFFFFu << (shift + 8));
            #pragma unroll
            for (int k = 0; k < 16; k++) {
                unsigned v = sval[k * 256 + tid];
                if ((v & hmask) == prefix) atomicAdd(&hist[(v >> shift) & 255u], 1u);
            }
            __syncthreads();
            suffix256_fast(hist, wtot, tid);
            unsigned sufd  = hist[tid];
            unsigned sufd1 = (tid < 255) ? hist[tid + 1] : 0u;
            if (sufd >= rank && sufd1 < rank) s_d = (unsigned)tid;
            __syncthreads();
            unsigned d = s_d;
            rank -= (d < 255) ? hist[d + 1] : 0u;
            prefix |= d << shift;
            __syncthreads();
        }
        res[r] = prefix;
    }
    if (tid == 0) {
        g_hi[ns] = res[0];
        g_lo[ns] = res[1];
    }
}

// ---------------- K2: 8px/thread count + warp-aggregated compaction (R10) ----
__global__ void __launch_bounds__(256) k_count(const float* __restrict__ tgt,
                                               const float* __restrict__ prd) {
    __shared__ unsigned scnt;
    __shared__ unsigned sred[8];
    __shared__ unsigned shist[256];
    int seg = blockIdx.x, n = blockIdx.y, sel = blockIdx.z;
    int ns = sel * NIMG + n;
    const float* img = (sel ? prd : tgt) + (size_t)n * HWSZ;
    unsigned hi = g_hi[ns], lo = g_lo[ns];
    unsigned width = hi - lo;
    unsigned s = bshift(width | 1u);
    int tid = threadIdx.x, lane = tid & 31, wid = tid >> 5;
    if (tid == 0) scnt = 0;
    shist[tid] = 0;
    __syncthreads();
    unsigned* seg_out = g_cand + (size_t)ns * CAPI + (size_t)seg * CAPB;
    unsigned above = 0;

    #pragma unroll 2
    for (int it = 0; it < 8; it++) {
        int i = seg * 32 + it * 4 + (tid >> 6);
        int j = (tid & 63) * 8;
        Oct o = load_oct(img, i, j, lane);
        float m2v[8]; oct_m2(o, m2v);
        unsigned vb[8], c = 0;
        bool isc[8];
        #pragma unroll
        for (int k = 0; k < 8; k++) {
            vb[k] = __float_as_uint(m2v[k]);
            above += (vb[k] > hi);
            isc[k] = ((vb[k] - lo - 1u) < width);
            c += isc[k];
        }
        unsigned inc = c;
        #pragma unroll
        for (int o2 = 1; o2 < 32; o2 <<= 1) {
            unsigned t = __shfl_up_sync(0xffffffffu, inc, o2);
            if (lane >= o2) inc += t;
        }
        unsigned tot = __shfl_sync(0xffffffffu, inc, 31);
        if (tot) {
            unsigned bb = 0;
            if (lane == 31) bb = atomicAdd(&scnt, tot);
            bb = __shfl_sync(0xffffffffu, bb, 31);
            unsigned off = bb + inc - c;
            #pragma unroll
            for (int k = 0; k < 8; k++)
                if (isc[k]) {
                    if (off < CAPB) {
                        seg_out[off] = vb[k];
                        atomicAdd(&shist[(vb[k] - lo - 1u) >> s], 1u);
                    }
                    off++;
                }
        }
    }
    #pragma unroll
    for (int o2 = 16; o2; o2 >>= 1) above += __shfl_down_sync(0xffffffffu, above, o2);
    if (lane == 0) sred[wid] = above;
    __syncthreads();
    if (shist[tid]) atomicAdd(&g_bhist[ns * 256 + tid], shist[tid]);
    if (tid == 0) {
        unsigned t = 0;
        #pragma unroll
        for (int w = 0; w < 8; w++) t += sred[w];
        atomicAdd(&g_above[ns], t);
        g_cnt[ns][seg] = min(scnt, (unsigned)CAPB);
    }
}

// ---------------- K3a: select prep — find bucket B and in-bucket rank r ------
__global__ void __launch_bounds__(256) k_selprep() {
    __shared__ unsigned hist[256];
    __shared__ unsigned wtot[8];
    __shared__ unsigned cnts[SEG];
    __shared__ unsigned s_d;
    int ns = blockIdx.x, tid = threadIdx.x;
    hist[tid] = g_bhist[ns * 256 + tid];
    if (tid < SEG) cnts[tid] = min(g_cnt[ns][tid], (unsigned)CAPB);
    __syncthreads();
    unsigned above = g_above[ns];
    long j = (long)AXK - (long)above;
    unsigned m = 0;
    #pragma unroll
    for (int ss = 0; ss < SEG; ss++) m += cnts[ss];
    if (j <= 0)               { if (tid == 0) { g_thr[ns] = g_hi[ns] + 1u; g_B[ns] = 0xFFFFFFFFu; } return; }
    if ((unsigned long)j > m) { if (tid == 0) { g_thr[ns] = g_lo[ns] + 1u; g_B[ns] = 0xFFFFFFFFu; } return; }

    suffix256_fast(hist, wtot, tid);
    unsigned sufd  = hist[tid];
    unsigned sufd1 = (tid < 255) ? hist[tid + 1] : 0u;
    if ((long)sufd >= j && (long)sufd1 < j) s_d = (unsigned)tid;
    __syncthreads();
    unsigned B = s_d;
    if (tid == 0) {
        g_B[ns] = B;
        g_r[ns] = (unsigned)(j - (long)((B < 255) ? hist[B + 1] : 0u));
    }
}

// ---------------- K3b: gather — one segment per block, keep bucket-B values --
__global__ void __launch_bounds__(256) k_selgather() {
    int sg = blockIdx.x, ns = blockIdx.y;
    unsigned B = g_B[ns];
    if (B == 0xFFFFFFFFu) return;
    unsigned lo = g_lo[ns], width = g_hi[ns] - lo;
    unsigned s = bshift(width | 1u);
    unsigned cnt = min(g_cnt[ns][sg], (unsigned)CAPB);
    const unsigned* segp = g_cand + (size_t)ns * CAPI + (size_t)sg * CAPB;
    unsigned* obuf = g_selbuf + (size_t)ns * SELCAP;
    int tid = threadIdx.x;
    for (unsigned idx = tid; idx < cnt; idx += 256) {
        unsigned v = segp[idx];
        if (((v - lo - 1u) >> s) == B) {
            unsigned pos = atomicAdd(&g_selcnt[ns], 1u);
            if (pos < SELCAP) obuf[pos] = v;
        }
    }
}

// ---------------- K3c: rank — exact r-th largest among gathered values -------
__global__ void __launch_bounds__(256) k_selrank() {
    __shared__ unsigned sbuf[SELCAP];
    __shared__ unsigned hist[256];
    __shared__ unsigned wtot[8];
    __shared__ unsigned cnts[SEG];
    __shared__ unsigned s_d, s_ans;
    int ns = blockIdx.x, tid = threadIdx.x;
    unsigned B = g_B[ns];
    if (B == 0xFFFFFFFFu) return;
    unsigned r = g_r[ns];
    unsigned mc = g_selcnt[ns];
    unsigned lo = g_lo[ns], width = g_hi[ns] - lo;
    unsigned s = bshift(width | 1u);

    if (mc <= SELCAP) {
        const unsigned* ibuf = g_selbuf + (size_t)ns * SELCAP;
        for (unsigned i = tid; i < mc; i += 256) sbuf[i] = ibuf[i];
        __syncthreads();
        for (unsigned i = tid; i < mc; i += 256) {
            unsigned v = sbuf[i], gt = 0, ge = 0;
            for (unsigned jx = 0; jx < mc; jx++) {
                unsigned u = sbuf[jx];
                gt += (u > v); ge += (u >= v);
            }
            if (gt < r && r <= ge) s_ans = v;
        }
        __syncthreads();
        if (tid == 0) g_thr[ns] = s_ans;
    } else {
        // fallback (practically never): radix over remaining delta bits
        if (tid < SEG) cnts[tid] = min(g_cnt[ns][tid], (unsigned)CAPB);
        __syncthreads();
        const unsigned* cand = g_cand + (size_t)ns * CAPI;
        unsigned kpref = B, rank = r;
        int sh = (int)s;
        while (sh > 0) {
            int nsh = sh - 8; if (nsh < 0) nsh = 0;
            unsigned wb = (unsigned)(sh - nsh);
            unsigned mask = (1u << wb) - 1u;
            __syncthreads();
            hist[tid] = 0;
            __syncthreads();
            for (int sg = 0; sg < SEG; sg++) {
                unsigned cnt = cnts[sg];
                const unsigned* segp = cand + sg * CAPB;
                for (unsigned idx = tid; idx < cnt; idx += 256) {
                    unsigned d = segp[idx] - lo - 1u;
                    if (d < width && (d >> sh) == kpref)
                        atomicAdd(&hist[(d >> nsh) & mask], 1u);
                }
            }
            __syncthreads();
            suffix256_fast(hist, wtot, tid);
            unsigned sd  = hist[tid];
            unsigned sd1 = (tid < 255) ? hist[tid + 1] : 0u;
            if (sd >= rank && sd1 < rank) s_d = (unsigned)tid;
            __syncthreads();
            unsigned d = s_d;
            rank -= (d < 255) ? hist[d + 1] : 0u;
            kpref = (kpref << wb) | d;
            sh = nsh;
            __syncthreads();
        }
        if (tid == 0) g_thr[ns] = lo + 1u + kpref;
    }
}

// ---------------- K4: distance-2 software-pipelined fused scatter-scan -------
__global__ void __launch_bounds__(128) k_scan(const float* __restrict__ tgt,
                                              const float* __restrict__ prd) {
    __shared__ float shT[NIMG], shP[NIMG];
    __shared__ float fred[4];
    int tid = threadIdx.x, lane = tid & 31, wid = tid >> 5;
    for (int k = tid; k < 2 * NIMG; k += 128) {
        float v = __uint_as_float(g_thr[k]);
        if (k < NIMG) shT[k] = v; else shP[k - NIMG] = v;
    }
    __syncthreads();

    int i = blockIdx.x;
    int j = tid * 4;
    bool lastrow  = (i == 511);
    bool edge_thr = (lane == 31);
    bool has_right = (j + 4) < 512;
    const float* tb = tgt + i * 512 + j;
    const float* pb = prd + i * 512 + j;

    float etf[4] = {0,0,0,0}, epf[4] = {0,0,0,0};
    float acc = 0.0f;

    RawQ rt0 = load_raw(tb,        lastrow, edge_thr, has_right);
    RawQ rp0 = load_raw(pb,        lastrow, edge_thr, has_right);
    RawQ rt1 = load_raw(tb + HWSZ, lastrow, edge_thr, has_right);
    RawQ rp1 = load_raw(pb + HWSZ, lastrow, edge_thr, has_right);
    const float* tq = tb + 2 * HWSZ;
    const float* pq = pb + 2 * HWSZ;

    #pragma unroll 2
    for (int n = 0; n < NIMG; n += 2) {
        RawQ rt2, rp2, rt3, rp3;
        rt2.ea = rt2.eb = rp2.ea = rp2.eb = 0.f;
        rt3.ea = rt3.eb = rp3.ea = rp3.eb = 0.f;
        if (n + 2 < NIMG) {
            rt2 = load_raw(tq,        lastrow, edge_thr, has_right);
            rp2 = load_raw(pq,        lastrow, edge_thr, has_right);
            rt3 = load_raw(tq + HWSZ, lastrow, edge_thr, has_right);
            rp3 = load_raw(pq + HWSZ, lastrow, edge_thr, has_right);
        }

        float mt[4], mp[4];
        raw_m2(rt0, lane, mt);
        raw_m2(rp0, lane, mp);
        float thT = shT[n], thP = shP[n];
        #pragma unroll
        for (int k = 0; k < 4; k++) {
            if (mt[k] >= thT) etf[k] = asqrt(mt[k]);   // float cmp == uint cmp (positives)
            if (mp[k] >= thP) epf[k] = asqrt(mp[k]);
            acc += __fdividef(fabsf(etf[k] - epf[k]), etf[k] + epf[k] + 1e-5f);
        }

        raw_m2(rt1, lane, mt);
        raw_m2(rp1, lane, mp);
        thT = shT[n + 1]; thP = shP[n + 1];
        #pragma unroll
        for (int k = 0; k < 4; k++) {
            if (mt[k] >= thT) etf[k] = asqrt(mt[k]);
            if (mp[k] >= thP) epf[k] = asqrt(mp[k]);
            acc += __fdividef(fabsf(etf[k] - epf[k]), etf[k] + epf[k] + 1e-5f);
        }

        rt0 = rt2; rp0 = rp2; rt1 = rt3; rp1 = rp3;
        tq += 2 * HWSZ; pq += 2 * HWSZ;
    }

    #pragma unroll
    for (int o = 16; o; o >>= 1) acc += __shfl_down_sync(0xffffffffu, acc, o);
    if (lane == 0) fred[wid] = acc;
    __syncthreads();
    if (tid == 0) atomicAdd(&g_acc, (double)(fred[0] + fred[1] + fred[2] + fred[3]));
}

// ---------------- K5: finalize ----------------
__global__ void k_final(const float* __restrict__ alpha, float* __restrict__ out) {
    out[0] = (float)((double)alpha[0] * g_acc / 33554432.0);
}

extern "C" void kernel_launch(void* const* d_in, const int* in_sizes, int n_in,
                              void* d_out, int out_size) {
    const float* pred  = (const float*)d_in[0];
    const float* tgt   = (const float*)d_in[1];
    const float* alpha = (const float*)d_in[2];
    float* out = (float*)d_out;

    k_bracket<<<dim3(NIMG, 2), 256>>>(tgt, pred);
    k_count<<<dim3(SEG, NIMG, 2), 256>>>(tgt, pred);
    k_selprep<<<2 * NIMG, 256>>>();
    k_selgather<<<dim3(SEG, 2 * NIMG), 256>>>();
    k_selrank<<<2 * NIMG, 256>>>();
    k_scan<<<512, 128>>>(tgt, pred);
    k_final<<<1, 1>>>(alpha, out);
}

// round 14
// speedup vs baseline: 1.0833x; 1.0833x over previous
#include <cuda_runtime.h>

#define HWSZ   262144
#define NIMG   128
#define AXK    26214
#define SEG    16
#define SUBS   16
#define CAPS   512
#define CAPI   (SEG*SUBS*CAPS)
#define SELCAP 3072
#define R_HI   260
#define R_LO   560

// ---------------- static scratch ----------------
__device__ unsigned g_cand[(size_t)2 * NIMG * CAPI];        // 128 MB, [ns][seg][sub][CAPS]
__device__ unsigned g_bhist[2 * NIMG * 256];
__device__ unsigned g_cnt3[2 * NIMG][SEG][SUBS];
__device__ unsigned g_above[2 * NIMG];
__device__ unsigned g_hi[2 * NIMG], g_lo[2 * NIMG], g_thr[2 * NIMG];
__device__ unsigned g_B[2 * NIMG], g_r[2 * NIMG], g_hb[2 * NIMG], g_selcnt[2 * NIMG];
__device__ unsigned g_selbuf[2 * NIMG * SELCAP];            // 3 MB
__device__ double   g_acc;

// Bit-identical squared Roberts magnitude everywhere (fixed op order).
__device__ __forceinline__ float m2_one(float a, float b, float c, float d) {
    float gx = a - d, gy = b - c;
    return fmaf(gx, gx, fmaf(gy, gy, 1e-12f));
}

__device__ __forceinline__ float asqrt(float x) {
    float r; asm("sqrt.approx.f32 %0, %1;" : "=f"(r) : "f"(x)); return r;
}

__device__ __forceinline__ unsigned bshift(unsigned width) {
    int hb = 32 - __clz(width - 1u);
    int s = hb - 8;
    return (s > 0) ? (unsigned)s : 0u;
}

__device__ __forceinline__ void quad_m2_rows(const float4& a, const float4& b,
                                             float ea, float eb, float out[4]) {
    out[0] = m2_one(a.x, a.y, b.x, b.y);
    out[1] = m2_one(a.y, a.z, b.y, b.z);
    out[2] = m2_one(a.z, a.w, b.z, b.w);
    out[3] = m2_one(a.w, ea,  b.w, eb);
}

// ---- 8-px horizontal "oct" (k_count) ----
struct Oct { float4 a0, b0, a1, b1; float ea, eb; };

__device__ __forceinline__ Oct load_oct(const float* __restrict__ img,
                                        int i, int j, int lane) {
    Oct o;
    const float* q = img + i * 512 + j;
    o.a0 = __ldg((const float4*)q);
    o.b0 = __ldg((const float4*)(q + 4));
    bool lastrow = (i == 511);
    if (!lastrow) {
        o.a1 = __ldg((const float4*)(q + 512));
        o.b1 = __ldg((const float4*)(q + 516));
    } else {
        o.a1 = make_float4(0.f, 0.f, 0.f, 0.f);
        o.b1 = make_float4(0.f, 0.f, 0.f, 0.f);
    }
    o.ea = __shfl_down_sync(0xffffffffu, o.a0.x, 1);
    o.eb = __shfl_down_sync(0xffffffffu, o.a1.x, 1);
    if (lane == 31) {
        bool hn = (j + 8) < 512;
        o.ea = hn ? __ldg(q + 8) : 0.0f;
        o.eb = (hn && !lastrow) ? __ldg(q + 520) : 0.0f;
    }
    return o;
}

__device__ __forceinline__ void oct_m2(const Oct& o, float m2[8]) {
    quad_m2_rows(o.a0, o.a1, o.b0.x, o.b1.x, m2);
    quad_m2_rows(o.b0, o.b1, o.ea,   o.eb,   m2 + 4);
}

// legacy single-quad loader (bracket only)
struct Quad { float4 v0, v1; float x4, y4; };
__device__ __forceinline__ Quad load_quad(const float* __restrict__ img, int p, int lane) {
    Quad q;
    int i = p >> 9, j = p & 511;
    q.v0 = __ldg((const float4*)(img + p));
    bool lastrow = (i == 511);
    q.v1 = lastrow ? make_float4(0.f, 0.f, 0.f, 0.f)
                   : __ldg((const float4*)(img + p + 512));
    q.x4 = __shfl_down_sync(0xffffffffu, q.v0.x, 1);
    q.y4 = __shfl_down_sync(0xffffffffu, q.v1.x, 1);
    if (lane == 31) {
        bool hn = (j + 4) < 512;
        q.x4 = hn ? __ldg(img + p + 4) : 0.0f;
        q.y4 = (hn && !lastrow) ? __ldg(img + p + 516) : 0.0f;
    }
    return q;
}
__device__ __forceinline__ void quad_m2(const Quad& q, float m2[4]) {
    m2[0] = m2_one(q.v0.x, q.v0.y, q.v1.x, q.v1.y);
    m2[1] = m2_one(q.v0.y, q.v0.z, q.v1.y, q.v1.z);
    m2[2] = m2_one(q.v0.z, q.v0.w, q.v1.z, q.v1.w);
    m2[3] = m2_one(q.v0.w, q.x4,   q.v1.w, q.y4);
}

// ---- raw 4px loads with NO shuffles (k_scan) ----
struct RawQ { float4 a, b; float ea, eb; };

__device__ __forceinline__ RawQ load_raw(const float* __restrict__ row0,
                                         bool lastrow, bool edge_thr, bool has_right) {
    RawQ r;
    r.a = __ldg((const float4*)row0);
    r.b = lastrow ? make_float4(0.f, 0.f, 0.f, 0.f)
                  : __ldg((const float4*)(row0 + 512));
    r.ea = 0.0f; r.eb = 0.0f;
    if (edge_thr && has_right) {
        r.ea = __ldg(row0 + 4);
        if (!lastrow) r.eb = __ldg(row0 + 516);
    }
    return r;
}

__device__ __forceinline__ void raw_m2(const RawQ& r, int lane, float out[4]) {
    float x4 = __shfl_down_sync(0xffffffffu, r.a.x, 1);
    float y4 = __shfl_down_sync(0xffffffffu, r.b.x, 1);
    if (lane == 31) { x4 = r.ea; y4 = r.eb; }
    out[0] = m2_one(r.a.x, r.a.y, r.b.x, r.b.y);
    out[1] = m2_one(r.a.y, r.a.z, r.b.y, r.b.z);
    out[2] = m2_one(r.a.z, r.a.w, r.b.z, r.b.w);
    out[3] = m2_one(r.a.w, x4,    r.b.w, y4);
}

// fast suffix sum of s[0..255] (warp shuffles, 2 syncs); blockDim>=256
__device__ __forceinline__ void suffix256_fast(unsigned* s, unsigned* wtot, int tid) {
    unsigned v = (tid < 256) ? s[tid] : 0u;
    int lane = tid & 31;
    #pragma unroll
    for (int off = 1; off < 32; off <<= 1) {
        unsigned t = __shfl_down_sync(0xffffffffu, v, off);
        if (lane + off < 32) v += t;
    }
    if (tid < 256 && lane == 0) wtot[tid >> 5] = v;
    __syncthreads();
    if (tid < 256) {
        unsigned hi = 0;
        int w = tid >> 5;
        #pragma unroll
        for (int x = 1; x < 8; x++) if (x > w) hi += wtot[x];
        s[tid] = v + hi;
    }
    __syncthreads();
}

// ---------------- K1: zero own counters + sampled bracket --------------------
__global__ void k_bracket(const float* __restrict__ tgt, const float* __restrict__ prd) {
    __shared__ unsigned sval[4096];
    __shared__ unsigned hist[256];
    __shared__ unsigned wtot[8];
    __shared__ unsigned s_d;
    int n = blockIdx.x, sel = blockIdx.y;
    int ns = sel * NIMG + n;
    const float* img = (sel ? prd : tgt) + (size_t)n * HWSZ;
    int tid = threadIdx.x, lane = tid & 31, wid = tid >> 5;

    g_bhist[ns * 256 + tid] = 0;
    ((unsigned*)g_cnt3[ns])[tid] = 0;                 // SEG*SUBS = 256 counters
    if (tid == 0) { g_above[ns] = 0; g_selcnt[ns] = 0; if (ns == 0) g_acc = 0.0; }

    #pragma unroll
    for (int k = 0; k < 4; k++) {
        int c   = k * 8 + wid;
        int row = (c * 509) & 511;
        int col = (c & 3) * 128;
        int p   = row * 512 + col + lane * 4;
        Quad q = load_quad(img, p, lane);
        float m2[4]; quad_m2(q, m2);
        int s = c * 128 + lane * 4;
        sval[s + 0] = __float_as_uint(m2[0]);
        sval[s + 1] = __float_as_uint(m2[1]);
        sval[s + 2] = __float_as_uint(m2[2]);
        sval[s + 3] = __float_as_uint(m2[3]);
    }
    __syncthreads();

    unsigned res[2]; const int ranks[2] = { R_HI, R_LO };
    for (int r = 0; r < 2; r++) {
        unsigned prefix = 0, rank = (unsigned)ranks[r];
        for (int shift = 24; shift >= 0; shift -= 8) {
            hist[tid] = 0;
            __syncthreads();
            unsigned hmask = (shift == 24) ? 0u : (0xFFFFFFFFu << (shift + 8));
            #pragma unroll
            for (int k = 0; k < 16; k++) {
                unsigned v = sval[k * 256 + tid];
                if ((v & hmask) == prefix) atomicAdd(&hist[(v >> shift) & 255u], 1u);
            }
            __syncthreads();
            suffix256_fast(hist, wtot, tid);
            unsigned sufd  = hist[tid];
            unsigned sufd1 = (tid < 255) ? hist[tid + 1] : 0u;
            if (sufd >= rank && sufd1 < rank) s_d = (unsigned)tid;
            __syncthreads();
            unsigned d = s_d;
            rank -= (d < 255) ? hist[d + 1] : 0u;
            prefix |= d << shift;
            __syncthreads();
        }
        res[r] = prefix;
    }
    if (tid == 0) {
        g_hi[ns] = res[0];
        g_lo[ns] = res[1];
    }
}

// ------- K2: 8px/thread count + sub-bucketed compaction + 256-bin hist -------
__global__ void __launch_bounds__(256) k_count(const float* __restrict__ tgt,
                                               const float* __restrict__ prd) {
    __shared__ unsigned scnt[SUBS];
    __shared__ unsigned sred[8];
    __shared__ unsigned shist[256];
    int seg = blockIdx.x, n = blockIdx.y, sel = blockIdx.z;
    int ns = sel * NIMG + n;
    const float* img = (sel ? prd : tgt) + (size_t)n * HWSZ;
    unsigned hi = g_hi[ns], lo = g_lo[ns];
    unsigned width = hi - lo;
    unsigned s = bshift(width | 1u);
    int tid = threadIdx.x, lane = tid & 31, wid = tid >> 5;
    if (tid < SUBS) scnt[tid] = 0;
    shist[tid] = 0;
    __syncthreads();
    unsigned* seg_base = g_cand + (size_t)ns * CAPI + (size_t)seg * (SUBS * CAPS);
    unsigned above = 0;

    #pragma unroll 2
    for (int it = 0; it < 8; it++) {
        int i = seg * 32 + it * 4 + (tid >> 6);
        int j = (tid & 63) * 8;
        Oct o = load_oct(img, i, j, lane);
        float m2v[8]; oct_m2(o, m2v);
        #pragma unroll
        for (int k = 0; k < 8; k++) {
            unsigned v = __float_as_uint(m2v[k]);
            above += (v > hi);
            unsigned d = v - lo - 1u;
            if (d < width) {
                unsigned b = d >> s;
                atomicAdd(&shist[b], 1u);                 // exact hist (even on overflow)
                unsigned sub = b >> 4;
                unsigned pos = atomicAdd(&scnt[sub], 1u);
                if (pos < CAPS) seg_base[sub * CAPS + pos] = v;
            }
        }
    }
    #pragma unroll
    for (int o2 = 16; o2; o2 >>= 1) above += __shfl_down_sync(0xffffffffu, above, o2);
    if (lane == 0) sred[wid] = above;
    __syncthreads();
    if (shist[tid]) atomicAdd(&g_bhist[ns * 256 + tid], shist[tid]);
    if (tid == 0) {
        unsigned t = 0;
        #pragma unroll
        for (int w = 0; w < 8; w++) t += sred[w];
        atomicAdd(&g_above[ns], t);
    }
    if (tid < SUBS) g_cnt3[ns][seg][tid] = min(scnt[tid], (unsigned)CAPS);
}

// ---------------- K3a: select prep — bucket B, rank r, bucket population -----
__global__ void __launch_bounds__(256) k_selprep() {
    __shared__ unsigned hist[256];
    __shared__ unsigned wtot[8];
    __shared__ unsigned s_d;
    int ns = blockIdx.x, tid = threadIdx.x;
    hist[tid] = g_bhist[ns * 256 + tid];
    __syncthreads();
    unsigned above = g_above[ns];
    long j = (long)AXK - (long)above;

    suffix256_fast(hist, wtot, tid);
    unsigned total = hist[0];
    if (j <= 0)                   { if (tid == 0) { g_thr[ns] = g_hi[ns] + 1u; g_B[ns] = 0xFFFFFFFFu; } return; }
    if ((unsigned long)j > total) { if (tid == 0) { g_thr[ns] = g_lo[ns] + 1u; g_B[ns] = 0xFFFFFFFFu; } return; }

    unsigned sufd  = hist[tid];
    unsigned sufd1 = (tid < 255) ? hist[tid + 1] : 0u;
    if ((long)sufd >= j && (long)sufd1 < j) s_d = (unsigned)tid;
    __syncthreads();
    unsigned B = s_d;
    if (tid == 0) {
        unsigned below = (B < 255) ? hist[B + 1] : 0u;
        g_B[ns]  = B;
        g_r[ns]  = (unsigned)(j - (long)below);
        g_hb[ns] = hist[B] - below;                       // exact bucket-B population
    }
}

// ---------------- K3b: gather — scan only sub B>>4 of each seg-block ---------
__global__ void __launch_bounds__(256) k_selgather() {
    int sg = blockIdx.x, ns = blockIdx.y;
    unsigned B = g_B[ns];
    if (B == 0xFFFFFFFFu) return;
    unsigned lo = g_lo[ns], width = g_hi[ns] - lo;
    unsigned s = bshift(width | 1u);
    unsigned sub = B >> 4;
    unsigned cnt = g_cnt3[ns][sg][sub];
    const unsigned* slice = g_cand + (size_t)ns * CAPI + (size_t)sg * (SUBS * CAPS)
                          + (size_t)sub * CAPS;
    unsigned* obuf = g_selbuf + (size_t)ns * SELCAP;
    int tid = threadIdx.x;
    for (unsigned idx = tid; idx < cnt; idx += 256) {
        unsigned v = slice[idx];
        if (((v - lo - 1u) >> s) == B) {
            unsigned pos = atomicAdd(&g_selcnt[ns], 1u);
            if (pos < SELCAP) obuf[pos] = v;
        }
    }
}

// ---------------- K3c: rank — exact r-th largest among gathered values -------
__global__ void __launch_bounds__(256) k_selrank() {
    __shared__ unsigned sbuf[SELCAP];
    __shared__ unsigned hist[256];
    __shared__ unsigned wtot[8];
    __shared__ unsigned s_d, s_ans;
    int ns = blockIdx.x, tid = threadIdx.x;
    unsigned B = g_B[ns];
    if (B == 0xFFFFFFFFu) return;
    unsigned r = g_r[ns];
    unsigned mc = g_selcnt[ns];
    unsigned lo = g_lo[ns], width = g_hi[ns] - lo;
    unsigned s = bshift(width | 1u);

    if (mc == g_hb[ns] && mc <= SELCAP) {
        // verified complete gather: exact rank by broadcast compare
        const unsigned* ibuf = g_selbuf + (size_t)ns * SELCAP;
        for (unsigned i = tid; i < mc; i += 256) sbuf[i] = ibuf[i];
        __syncthreads();
        for (unsigned i = tid; i < mc; i += 256) {
            unsigned v = sbuf[i], gt = 0, ge = 0;
            for (unsigned jx = 0; jx < mc; jx++) {
                unsigned u = sbuf[jx];
                gt += (u > v); ge += (u >= v);
            }
            if (gt < r && r <= ge) s_ans = v;
        }
        __syncthreads();
        if (tid == 0) g_thr[ns] = s_ans;
    } else {
        // fallback (practically never): radix over all stored slices
        const unsigned* cand = g_cand + (size_t)ns * CAPI;
        unsigned kpref = B, rank = r;
        int sh = (int)s;
        while (sh > 0) {
            int nsh = sh - 8; if (nsh < 0) nsh = 0;
            unsigned wb = (unsigned)(sh - nsh);
            unsigned mask = (1u << wb) - 1u;
            __syncthreads();
            hist[tid] = 0;
            __syncthreads();
            for (int sg = 0; sg < SEG; sg++) {
                for (int sub = 0; sub < SUBS; sub++) {
                    unsigned cnt = g_cnt3[ns][sg][sub];
                    const unsigned* slice = cand + (size_t)sg * (SUBS * CAPS)
                                          + (size_t)sub * CAPS;
                    for (unsigned idx = tid; idx < cnt; idx += 256) {
                        unsigned d = slice[idx] - lo - 1u;
                        if (d < width && (d >> sh) == kpref)
                            atomicAdd(&hist[(d >> nsh) & mask], 1u);
                    }
                }
            }
            __syncthreads();
            suffix256_fast(hist, wtot, tid);
            unsigned sd  = hist[tid];
            unsigned sd1 = (tid < 255) ? hist[tid + 1] : 0u;
            if (sd >= rank && sd1 < rank) s_d = (unsigned)tid;
            __syncthreads();
            unsigned d = s_d;
            rank -= (d < 255) ? hist[d + 1] : 0u;
            kpref = (kpref << wb) | d;
            sh = nsh;
            __syncthreads();
        }
        if (tid == 0) g_thr[ns] = lo + 1u + kpref;
    }
}

// ---------------- K4: distance-2 software-pipelined fused scatter-scan -------
__global__ void __launch_bounds__(128) k_scan(const float* __restrict__ tgt,
                                              const float* __restrict__ prd) {
    __shared__ float shT[NIMG], shP[NIMG];
    __shared__ float fred[4];
    int tid = threadIdx.x, lane = tid & 31, wid = tid >> 5;
    for (int k = tid; k < 2 * NIMG; k += 128) {
        float v = __uint_as_float(g_thr[k]);
        if (k < NIMG) shT[k] = v; else shP[k - NIMG] = v;
    }
    __syncthreads();

    int i = blockIdx.x;
    int j = tid * 4;
    bool lastrow  = (i == 511);
    bool edge_thr = (lane == 31);
    bool has_right = (j + 4) < 512;
    const float* tb = tgt + i * 512 + j;
    const float* pb = prd + i * 512 + j;

    float etf[4] = {0,0,0,0}, epf[4] = {0,0,0,0};
    float acc = 0.0f;

    RawQ rt0 = load_raw(tb,        lastrow, edge_thr, has_right);
    RawQ rp0 = load_raw(pb,        lastrow, edge_thr, has_right);
    RawQ rt1 = load_raw(tb + HWSZ, lastrow, edge_thr, has_right);
    RawQ rp1 = load_raw(pb + HWSZ, lastrow, edge_thr, has_right);
    const float* tq = tb + 2 * HWSZ;
    const float* pq = pb + 2 * HWSZ;

    #pragma unroll 2
    for (int n = 0; n < NIMG; n += 2) {
        RawQ rt2, rp2, rt3, rp3;
        rt2.ea = rt2.eb = rp2.ea = rp2.eb = 0.f;
        rt3.ea = rt3.eb = rp3.ea = rp3.eb = 0.f;
        if (n + 2 < NIMG) {
            rt2 = load_raw(tq,        lastrow, edge_thr, has_right);
            rp2 = load_raw(pq,        lastrow, edge_thr, has_right);
            rt3 = load_raw(tq + HWSZ, lastrow, edge_thr, has_right);
            rp3 = load_raw(pq + HWSZ, lastrow, edge_thr, has_right);
        }

        float mt[4], mp[4];
        raw_m2(rt0, lane, mt);
        raw_m2(rp0, lane, mp);
        float thT = shT[n], thP = shP[n];
        #pragma unroll
        for (int k = 0; k < 4; k++) {
            if (mt[k] >= thT) etf[k] = asqrt(mt[k]);
            if (mp[k] >= thP) epf[k] = asqrt(mp[k]);
            acc += __fdividef(fabsf(etf[k] - epf[k]), etf[k] + epf[k] + 1e-5f);
        }

        raw_m2(rt1, lane, mt);
        raw_m2(rp1, lane, mp);
        thT = shT[n + 1]; thP = shP[n + 1];
        #pragma unroll
        for (int k = 0; k < 4; k++) {
            if (mt[k] >= thT) etf[k] = asqrt(mt[k]);
            if (mp[k] >= thP) epf[k] = asqrt(mp[k]);
            acc += __fdividef(fabsf(etf[k] - epf[k]), etf[k] + epf[k] + 1e-5f);
        }

        rt0 = rt2; rp0 = rp2; rt1 = rt3; rp1 = rp3;
        tq += 2 * HWSZ; pq += 2 * HWSZ;
    }

    #pragma unroll
    for (int o = 16; o; o >>= 1) acc += __shfl_down_sync(0xffffffffu, acc, o);
    if (lane == 0) fred[wid] = acc;
    __syncthreads();
    if (tid == 0) atomicAdd(&g_acc, (double)(fred[0] + fred[1] + fred[2] + fred[3]));
}

// ---------------- K5: finalize ----------------
__global__ void k_final(const float* __restrict__ alpha, float* __restrict__ out) {
    out[0] = (float)((double)alpha[0] * g_acc / 33554432.0);
}

extern "C" void kernel_launch(void* const* d_in, const int* in_sizes, int n_in,
                              void* d_out, int out_size) {
    const float* pred  = (const float*)d_in[0];
    const float* tgt   = (const float*)d_in[1];
    const float* alpha = (const float*)d_in[2];
    float* out = (float*)d_out;

    k_bracket<<<dim3(NIMG, 2), 256>>>(tgt, pred);
    k_count<<<dim3(SEG, NIMG, 2), 256>>>(tgt, pred);
    k_selprep<<<2 * NIMG, 256>>>();
    k_selgather<<<dim3(SEG, 2 * NIMG), 256>>>();
    k_selrank<<<2 * NIMG, 256>>>();
    k_scan<<<512, 128>>>(tgt, pred);
    k_final<<<1, 1>>>(alpha, out);
}

// round 15
// speedup vs baseline: 1.0963x; 1.0120x over previous
#include <cuda_runtime.h>

#define HWSZ   262144
#define NIMG   128
#define AXK    26214
#define SEG    16
#define SUBS   16
#define CAPS   512
#define CAPI   (SEG*SUBS*CAPS)
#define SELCAP 3072
#define R_HI   260
#define R_LO   560

// ---------------- static scratch ----------------
__device__ unsigned g_cand[(size_t)2 * NIMG * CAPI];        // 128 MB, [ns][seg][sub][CAPS]
__device__ unsigned g_bhist[2 * NIMG * 256];
__device__ unsigned g_cnt3[2 * NIMG][SEG][SUBS];
__device__ unsigned g_above[2 * NIMG];
__device__ unsigned g_hi[2 * NIMG], g_lo[2 * NIMG], g_thr[2 * NIMG];
__device__ double   g_acc;

// Bit-identical squared Roberts magnitude everywhere (fixed op order).
__device__ __forceinline__ float m2_one(float a, float b, float c, float d) {
    float gx = a - d, gy = b - c;
    return fmaf(gx, gx, fmaf(gy, gy, 1e-12f));
}

__device__ __forceinline__ float asqrt(float x) {
    float r; asm("sqrt.approx.f32 %0, %1;" : "=f"(r) : "f"(x)); return r;
}

__device__ __forceinline__ unsigned bshift(unsigned width) {
    int hb = 32 - __clz(width - 1u);
    int s = hb - 8;
    return (s > 0) ? (unsigned)s : 0u;
}

__device__ __forceinline__ void quad_m2_rows(const float4& a, const float4& b,
                                             float ea, float eb, float out[4]) {
    out[0] = m2_one(a.x, a.y, b.x, b.y);
    out[1] = m2_one(a.y, a.z, b.y, b.z);
    out[2] = m2_one(a.z, a.w, b.z, b.w);
    out[3] = m2_one(a.w, ea,  b.w, eb);
}

// ---- 8-px horizontal "oct" (k_count) ----
struct Oct { float4 a0, b0, a1, b1; float ea, eb; };

__device__ __forceinline__ Oct load_oct(const float* __restrict__ img,
                                        int i, int j, int lane) {
    Oct o;
    const float* q = img + i * 512 + j;
    o.a0 = __ldg((const float4*)q);
    o.b0 = __ldg((const float4*)(q + 4));
    bool lastrow = (i == 511);
    if (!lastrow) {
        o.a1 = __ldg((const float4*)(q + 512));
        o.b1 = __ldg((const float4*)(q + 516));
    } else {
        o.a1 = make_float4(0.f, 0.f, 0.f, 0.f);
        o.b1 = make_float4(0.f, 0.f, 0.f, 0.f);
    }
    o.ea = __shfl_down_sync(0xffffffffu, o.a0.x, 1);
    o.eb = __shfl_down_sync(0xffffffffu, o.a1.x, 1);
    if (lane == 31) {
        bool hn = (j + 8) < 512;
        o.ea = hn ? __ldg(q + 8) : 0.0f;
        o.eb = (hn && !lastrow) ? __ldg(q + 520) : 0.0f;
    }
    return o;
}

__device__ __forceinline__ void oct_m2(const Oct& o, float m2[8]) {
    quad_m2_rows(o.a0, o.a1, o.b0.x, o.b1.x, m2);
    quad_m2_rows(o.b0, o.b1, o.ea,   o.eb,   m2 + 4);
}

// legacy single-quad loader (bracket only)
struct Quad { float4 v0, v1; float x4, y4; };
__device__ __forceinline__ Quad load_quad(const float* __restrict__ img, int p, int lane) {
    Quad q;
    int i = p >> 9, j = p & 511;
    q.v0 = __ldg((const float4*)(img + p));
    bool lastrow = (i == 511);
    q.v1 = lastrow ? make_float4(0.f, 0.f, 0.f, 0.f)
                   : __ldg((const float4*)(img + p + 512));
    q.x4 = __shfl_down_sync(0xffffffffu, q.v0.x, 1);
    q.y4 = __shfl_down_sync(0xffffffffu, q.v1.x, 1);
    if (lane == 31) {
        bool hn = (j + 4) < 512;
        q.x4 = hn ? __ldg(img + p + 4) : 0.0f;
        q.y4 = (hn && !lastrow) ? __ldg(img + p + 516) : 0.0f;
    }
    return q;
}
__device__ __forceinline__ void quad_m2(const Quad& q, float m2[4]) {
    m2[0] = m2_one(q.v0.x, q.v0.y, q.v1.x, q.v1.y);
    m2[1] = m2_one(q.v0.y, q.v0.z, q.v1.y, q.v1.z);
    m2[2] = m2_one(q.v0.z, q.v0.w, q.v1.z, q.v1.w);
    m2[3] = m2_one(q.v0.w, q.x4,   q.v1.w, q.y4);
}

// ---- raw 4px loads with NO shuffles (k_scan) ----
struct RawQ { float4 a, b; float ea, eb; };

__device__ __forceinline__ RawQ load_raw(const float* __restrict__ row0,
                                         bool lastrow, bool edge_thr, bool has_right) {
    RawQ r;
    r.a = __ldg((const float4*)row0);
    r.b = lastrow ? make_float4(0.f, 0.f, 0.f, 0.f)
                  : __ldg((const float4*)(row0 + 512));
    r.ea = 0.0f; r.eb = 0.0f;
    if (edge_thr && has_right) {
        r.ea = __ldg(row0 + 4);
        if (!lastrow) r.eb = __ldg(row0 + 516);
    }
    return r;
}

__device__ __forceinline__ void raw_m2(const RawQ& r, int lane, float out[4]) {
    float x4 = __shfl_down_sync(0xffffffffu, r.a.x, 1);
    float y4 = __shfl_down_sync(0xffffffffu, r.b.x, 1);
    if (lane == 31) { x4 = r.ea; y4 = r.eb; }
    out[0] = m2_one(r.a.x, r.a.y, r.b.x, r.b.y);
    out[1] = m2_one(r.a.y, r.a.z, r.b.y, r.b.z);
    out[2] = m2_one(r.a.z, r.a.w, r.b.z, r.b.w);
    out[3] = m2_one(r.a.w, x4,    r.b.w, y4);
}

// fast suffix sum of s[0..255] (warp shuffles, 2 syncs); blockDim>=256
__device__ __forceinline__ void suffix256_fast(unsigned* s, unsigned* wtot, int tid) {
    unsigned v = (tid < 256) ? s[tid] : 0u;
    int lane = tid & 31;
    #pragma unroll
    for (int off = 1; off < 32; off <<= 1) {
        unsigned t = __shfl_down_sync(0xffffffffu, v, off);
        if (lane + off < 32) v += t;
    }
    if (tid < 256 && lane == 0) wtot[tid >> 5] = v;
    __syncthreads();
    if (tid < 256) {
        unsigned hi = 0;
        int w = tid >> 5;
        #pragma unroll
        for (int x = 1; x < 8; x++) if (x > w) hi += wtot[x];
        s[tid] = v + hi;
    }
    __syncthreads();
}

// ---------------- K1: zero own counters + sampled bracket --------------------
__global__ void k_bracket(const float* __restrict__ tgt, const float* __restrict__ prd) {
    __shared__ unsigned sval[4096];
    __shared__ unsigned hist[256];
    __shared__ unsigned wtot[8];
    __shared__ unsigned s_d;
    int n = blockIdx.x, sel = blockIdx.y;
    int ns = sel * NIMG + n;
    const float* img = (sel ? prd : tgt) + (size_t)n * HWSZ;
    int tid = threadIdx.x, lane = tid & 31, wid = tid >> 5;

    g_bhist[ns * 256 + tid] = 0;
    ((unsigned*)g_cnt3[ns])[tid] = 0;                 // SEG*SUBS = 256 counters
    if (tid == 0) { g_above[ns] = 0; if (ns == 0) g_acc = 0.0; }

    #pragma unroll
    for (int k = 0; k < 4; k++) {
        int c   = k * 8 + wid;
        int row = (c * 509) & 511;
        int col = (c & 3) * 128;
        int p   = row * 512 + col + lane * 4;
        Quad q = load_quad(img, p, lane);
        float m2[4]; quad_m2(q, m2);
        int s = c * 128 + lane * 4;
        sval[s + 0] = __float_as_uint(m2[0]);
        sval[s + 1] = __float_as_uint(m2[1]);
        sval[s + 2] = __float_as_uint(m2[2]);
        sval[s + 3] = __float_as_uint(m2[3]);
    }
    __syncthreads();

    unsigned res[2]; const int ranks[2] = { R_HI, R_LO };
    for (int r = 0; r < 2; r++) {
        unsigned prefix = 0, rank = (unsigned)ranks[r];
        for (int shift = 24; shift >= 0; shift -= 8) {
            hist[tid] = 0;
            __syncthreads();
            unsigned hmask = (shift == 24) ? 0u : (0xFFFFFFFFu << (shift + 8));
            #pragma unroll
            for (int k = 0; k < 16; k++) {
                unsigned v = sval[k * 256 + tid];
                if ((v & hmask) == prefix) atomicAdd(&hist[(v >> shift) & 255u], 1u);
            }
            __syncthreads();
            suffix256_fast(hist, wtot, tid);
            unsigned sufd  = hist[tid];
            unsigned sufd1 = (tid < 255) ? hist[tid + 1] : 0u;
            if (sufd >= rank && sufd1 < rank) s_d = (unsigned)tid;
            __syncthreads();
            unsigned d = s_d;
            rank -= (d < 255) ? hist[d + 1] : 0u;
            prefix |= d << shift;
            __syncthreads();
        }
        res[r] = prefix;
    }
    if (tid == 0) {
        g_hi[ns] = res[0];
        g_lo[ns] = res[1];
    }
}

// ------- K2: 8px/thread count + sub-bucketed compaction + 256-bin hist -------
__global__ void __launch_bounds__(256) k_count(const float* __restrict__ tgt,
                                               const float* __restrict__ prd) {
    __shared__ unsigned scnt[SUBS];
    __shared__ unsigned sred[8];
    __shared__ unsigned shist[256];
    int seg = blockIdx.x, n = blockIdx.y, sel = blockIdx.z;
    int ns = sel * NIMG + n;
    const float* img = (sel ? prd : tgt) + (size_t)n * HWSZ;
    unsigned hi = g_hi[ns], lo = g_lo[ns];
    unsigned width = hi - lo;
    unsigned s = bshift(width | 1u);
    int tid = threadIdx.x, lane = tid & 31, wid = tid >> 5;
    if (tid < SUBS) scnt[tid] = 0;
    shist[tid] = 0;
    __syncthreads();
    unsigned* seg_base = g_cand + (size_t)ns * CAPI + (size_t)seg * (SUBS * CAPS);
    unsigned above = 0;

    #pragma unroll 2
    for (int it = 0; it < 8; it++) {
        int i = seg * 32 + it * 4 + (tid >> 6);
        int j = (tid & 63) * 8;
        Oct o = load_oct(img, i, j, lane);
        float m2v[8]; oct_m2(o, m2v);
        #pragma unroll
        for (int k = 0; k < 8; k++) {
            unsigned v = __float_as_uint(m2v[k]);
            above += (v > hi);
            unsigned d = v - lo - 1u;
            if (d < width) {
                unsigned b = d >> s;
                atomicAdd(&shist[b], 1u);                 // exact hist (even on overflow)
                unsigned sub = b >> 4;
                unsigned pos = atomicAdd(&scnt[sub], 1u);
                if (pos < CAPS) seg_base[sub * CAPS + pos] = v;
            }
        }
    }
    #pragma unroll
    for (int o2 = 16; o2; o2 >>= 1) above += __shfl_down_sync(0xffffffffu, above, o2);
    if (lane == 0) sred[wid] = above;
    __syncthreads();
    if (shist[tid]) atomicAdd(&g_bhist[ns * 256 + tid], shist[tid]);
    if (tid == 0) {
        unsigned t = 0;
        #pragma unroll
        for (int w = 0; w < 8; w++) t += sred[w];
        atomicAdd(&g_above[ns], t);
    }
    if (tid < SUBS) g_cnt3[ns][seg][tid] = min(scnt[tid], (unsigned)CAPS);
}

// -------- K3: fused exact select — hist → B/r → slice gather → rank ----------
__global__ void __launch_bounds__(256) k_select() {
    __shared__ unsigned hist[256];
    __shared__ unsigned wtot[8];
    __shared__ unsigned sbuf[SELCAP];
    __shared__ unsigned cnts[SEG];
    __shared__ unsigned s_d, s_cnt, s_ans;
    int ns = blockIdx.x, tid = threadIdx.x;
    hist[tid] = g_bhist[ns * 256 + tid];
    if (tid == 0) s_cnt = 0;
    __syncthreads();
    unsigned above = g_above[ns];
    long j = (long)AXK - (long)above;

    suffix256_fast(hist, wtot, tid);
    unsigned total = hist[0];
    if (j <= 0)                   { if (tid == 0) g_thr[ns] = g_hi[ns] + 1u; return; }
    if ((unsigned long)j > total) { if (tid == 0) g_thr[ns] = g_lo[ns] + 1u; return; }

    unsigned sufd  = hist[tid];
    unsigned sufd1 = (tid < 255) ? hist[tid + 1] : 0u;
    if ((long)sufd >= j && (long)sufd1 < j) s_d = (unsigned)tid;
    __syncthreads();
    unsigned B = s_d;
    unsigned below = (B < 255) ? hist[B + 1] : 0u;
    unsigned r  = (unsigned)(j - (long)below);
    unsigned hb = hist[B] - below;                    // exact bucket-B population
    __syncthreads();

    unsigned lo = g_lo[ns], width = g_hi[ns] - lo;
    unsigned s = bshift(width | 1u);
    unsigned sub = B >> 4;
    const unsigned* cand = g_cand + (size_t)ns * CAPI;

    // load per-seg slice counts for sub, then gather bucket-B values into smem
    if (tid < SEG) cnts[tid] = g_cnt3[ns][tid][sub];
    __syncthreads();
    #pragma unroll
    for (int sg = 0; sg < SEG; sg++) {
        unsigned cnt = cnts[sg];
        const unsigned* slice = cand + (size_t)sg * (SUBS * CAPS) + (size_t)sub * CAPS;
        for (unsigned idx = tid; idx < cnt; idx += 256) {
            unsigned v = slice[idx];
            if (((v - lo - 1u) >> s) == B) {
                unsigned pos = atomicAdd(&s_cnt, 1u);
                if (pos < SELCAP) sbuf[pos] = v;
            }
        }
    }
    __syncthreads();
    unsigned mc = s_cnt;

    if (mc == hb && mc <= SELCAP) {
        // verified complete gather: exact rank by broadcast compare
        for (unsigned i = tid; i < mc; i += 256) {
            unsigned v = sbuf[i], gt = 0, ge = 0;
            for (unsigned jx = 0; jx < mc; jx++) {
                unsigned u = sbuf[jx];
                gt += (u > v); ge += (u >= v);
            }
            if (gt < r && r <= ge) s_ans = v;
        }
        __syncthreads();
        if (tid == 0) g_thr[ns] = s_ans;
    } else {
        // fallback (practically never): radix over all stored slices
        unsigned kpref = B, rank = r;
        int sh = (int)s;
        while (sh > 0) {
            int nsh = sh - 8; if (nsh < 0) nsh = 0;
            unsigned wb = (unsigned)(sh - nsh);
            unsigned mask = (1u << wb) - 1u;
            __syncthreads();
            hist[tid] = 0;
            __syncthreads();
            for (int sg = 0; sg < SEG; sg++) {
                for (int sb = 0; sb < SUBS; sb++) {
                    unsigned cnt = g_cnt3[ns][sg][sb];
                    const unsigned* slice = cand + (size_t)sg * (SUBS * CAPS)
                                          + (size_t)sb * CAPS;
                    for (unsigned idx = tid; idx < cnt; idx += 256) {
                        unsigned d = slice[idx] - lo - 1u;
                        if (d < width && (d >> sh) == kpref)
                            atomicAdd(&hist[(d >> nsh) & mask], 1u);
                    }
                }
            }
            __syncthreads();
            suffix256_fast(hist, wtot, tid);
            unsigned sd  = hist[tid];
            unsigned sd1 = (tid < 255) ? hist[tid + 1] : 0u;
            if (sd >= rank && sd1 < rank) s_d = (unsigned)tid;
            __syncthreads();
            unsigned d = s_d;
            rank -= (d < 255) ? hist[d + 1] : 0u;
            kpref = (kpref << wb) | d;
            sh = nsh;
            __syncthreads();
        }
        if (tid == 0) g_thr[ns] = lo + 1u + kpref;
    }
}

// ---------------- K4: distance-2 software-pipelined fused scatter-scan -------
__global__ void __launch_bounds__(128) k_scan(const float* __restrict__ tgt,
                                              const float* __restrict__ prd) {
    __shared__ float shT[NIMG], shP[NIMG];
    __shared__ float fred[4];
    int tid = threadIdx.x, lane = tid & 31, wid = tid >> 5;
    for (int k = tid; k < 2 * NIMG; k += 128) {
        float v = __uint_as_float(g_thr[k]);
        if (k < NIMG) shT[k] = v; else shP[k - NIMG] = v;
    }
    __syncthreads();

    int i = blockIdx.x;
    int j = tid * 4;
    bool lastrow  = (i == 511);
    bool edge_thr = (lane == 31);
    bool has_right = (j + 4) < 512;
    const float* tb = tgt + i * 512 + j;
    const float* pb = prd + i * 512 + j;

    float etf[4] = {0,0,0,0}, epf[4] = {0,0,0,0};
    float acc = 0.0f;

    RawQ rt0 = load_raw(tb,        lastrow, edge_thr, has_right);
    RawQ rp0 = load_raw(pb,        lastrow, edge_thr, has_right);
    RawQ rt1 = load_raw(tb + HWSZ, lastrow, edge_thr, has_right);
    RawQ rp1 = load_raw(pb + HWSZ, lastrow, edge_thr, has_right);
    const float* tq = tb + 2 * HWSZ;
    const float* pq = pb + 2 * HWSZ;

    #pragma unroll 2
    for (int n = 0; n < NIMG; n += 2) {
        RawQ rt2, rp2, rt3, rp3;
        rt2.ea = rt2.eb = rp2.ea = rp2.eb = 0.f;
        rt3.ea = rt3.eb = rp3.ea = rp3.eb = 0.f;
        if (n + 2 < NIMG) {
            rt2 = load_raw(tq,        lastrow, edge_thr, has_right);
            rp2 = load_raw(pq,        lastrow, edge_thr, has_right);
            rt3 = load_raw(tq + HWSZ, lastrow, edge_thr, has_right);
            rp3 = load_raw(pq + HWSZ, lastrow, edge_thr, has_right);
        }

        float mt[4], mp[4];
        raw_m2(rt0, lane, mt);
        raw_m2(rp0, lane, mp);
        float thT = shT[n], thP = shP[n];
        #pragma unroll
        for (int k = 0; k < 4; k++) {
            if (mt[k] >= thT) etf[k] = asqrt(mt[k]);
            if (mp[k] >= thP) epf[k] = asqrt(mp[k]);
            acc += __fdividef(fabsf(etf[k] - epf[k]), etf[k] + epf[k] + 1e-5f);
        }

        raw_m2(rt1, lane, mt);
        raw_m2(rp1, lane, mp);
        thT = shT[n + 1]; thP = shP[n + 1];
        #pragma unroll
        for (int k = 0; k < 4; k++) {
            if (mt[k] >= thT) etf[k] = asqrt(mt[k]);
            if (mp[k] >= thP) epf[k] = asqrt(mp[k]);
            acc += __fdividef(fabsf(etf[k] - epf[k]), etf[k] + epf[k] + 1e-5f);
        }

        rt0 = rt2; rp0 = rp2; rt1 = rt3; rp1 = rp3;
        tq += 2 * HWSZ; pq += 2 * HWSZ;
    }

    #pragma unroll
    for (int o = 16; o; o >>= 1) acc += __shfl_down_sync(0xffffffffu, acc, o);
    if (lane == 0) fred[wid] = acc;
    __syncthreads();
    if (tid == 0) atomicAdd(&g_acc, (double)(fred[0] + fred[1] + fred[2] + fred[3]));
}

// ---------------- K5: finalize ----------------
__global__ void k_final(const float* __restrict__ alpha, float* __restrict__ out) {
    out[0] = (float)((double)alpha[0] * g_acc / 33554432.0);
}

extern "C" void kernel_launch(void* const* d_in, const int* in_sizes, int n_in,
                              void* d_out, int out_size) {
    const float* pred  = (const float*)d_in[0];
    const float* tgt   = (const float*)d_in[1];
    const float* alpha = (const float*)d_in[2];
    float* out = (float*)d_out;

    k_bracket<<<dim3(NIMG, 2), 256>>>(tgt, pred);
    k_count<<<dim3(SEG, NIMG, 2), 256>>>(tgt, pred);
    k_select<<<2 * NIMG, 256>>>();
    k_scan<<<512, 128>>>(tgt, pred);
    k_final<<<1, 1>>>(alpha, out);
}